// round 6
// baseline (speedup 1.0000x reference)
#include <cuda_runtime.h>
#include <cuda_fp16.h>
#include <math.h>
#include <stdint.h>

// ---------------- problem constants ----------------
#define HDIM    2048
#define NE      64           // experts (GEMM N)
#define TM      64           // tokens per CTA (GEMM M)
#define KB      32           // K per chunk (halfs)
#define NCH     (HDIM/KB)    // 64
#define THREADS 128
#define GAP_TH  1e-3f
#define FLAG_CAP 4096

#define RP 20                 // row pitch in u32 (16 data + 4 pad)
#define LSP 65

__device__ float g_eload[NE];
__device__ float g_zsum;
__device__ int   g_nflag;
__device__ int   g_flags[FLAG_CAP];
__device__ float g_flag_lg[FLAG_CAP][NE];
// precomputed W split: [e][k/2] half2 as u32
__device__ uint32_t g_whi[NE * HDIM / 2];
__device__ uint32_t g_wlo[NE * HDIM / 2];

__global__ void zero_kernel() {
    int t = threadIdx.x;
    if (t < NE) g_eload[t] = 0.0f;
    if (t == 0) { g_zsum = 0.0f; g_nflag = 0; }
}

// ---- one-time W hi/lo split (64 blocks x 256 thr) ----
__global__ __launch_bounds__(256) void prep_kernel(const float* __restrict__ W) {
    const int e = blockIdx.x;
    const int tid = threadIdx.x;
    const float* wr = &W[(size_t)e * HDIM + tid * 8];
    float4 v0 = *reinterpret_cast<const float4*>(wr);
    float4 v1 = *reinterpret_cast<const float4*>(wr + 4);
    uint32_t hi[4], lo[4];
    float4 vv[2] = {v0, v1};
#pragma unroll
    for (int i = 0; i < 2; i++) {
        __half2 h0 = __floats2half2_rn(vv[i].x, vv[i].y);
        __half2 h1 = __floats2half2_rn(vv[i].z, vv[i].w);
        float2 f0 = __half22float2(h0);
        float2 f1 = __half22float2(h1);
        __half2 l0 = __floats2half2_rn(vv[i].x - f0.x, vv[i].y - f0.y);
        __half2 l1 = __floats2half2_rn(vv[i].z - f1.x, vv[i].w - f1.y);
        hi[i * 2]     = *reinterpret_cast<uint32_t*>(&h0);
        hi[i * 2 + 1] = *reinterpret_cast<uint32_t*>(&h1);
        lo[i * 2]     = *reinterpret_cast<uint32_t*>(&l0);
        lo[i * 2 + 1] = *reinterpret_cast<uint32_t*>(&l1);
    }
    *reinterpret_cast<uint4*>(&g_whi[e * (HDIM / 2) + tid * 4]) = *reinterpret_cast<uint4*>(hi);
    *reinterpret_cast<uint4*>(&g_wlo[e * (HDIM / 2) + tid * 4]) = *reinterpret_cast<uint4*>(lo);
}

__device__ __forceinline__ void mma_f32acc(float* d, const uint32_t* a, uint32_t b0, uint32_t b1) {
    asm volatile(
        "mma.sync.aligned.m16n8k16.row.col.f32.f16.f16.f32 "
        "{%0,%1,%2,%3}, {%4,%5,%6,%7}, {%8,%9}, {%0,%1,%2,%3};"
        : "+f"(d[0]), "+f"(d[1]), "+f"(d[2]), "+f"(d[3])
        : "r"(a[0]), "r"(a[1]), "r"(a[2]), "r"(a[3]), "r"(b0), "r"(b1));
}
__device__ __forceinline__ void mma_f16acc(uint32_t* d, const uint32_t* a, uint32_t b0, uint32_t b1) {
    asm volatile(
        "mma.sync.aligned.m16n8k16.row.col.f16.f16.f16.f16 "
        "{%0,%1}, {%2,%3,%4,%5}, {%6,%7}, {%0,%1};"
        : "+r"(d[0]), "+r"(d[1])
        : "r"(a[0]), "r"(a[1]), "r"(a[2]), "r"(a[3]), "r"(b0), "r"(b1));
}

__global__ __launch_bounds__(THREADS, 3) void gate_kernel(
    const float* __restrict__ x, const float* __restrict__ W,
    float* __restrict__ out, int N)
{
    __shared__ union {
        uint32_t tiles[2][4][TM * RP];    // [buf][AH,AL,BH,BL]
        float    ls[TM][LSP];
    } sm;

    const int tid  = threadIdx.x;
    const int wid  = tid >> 5;
    const int lane = tid & 31;
    const int grp  = lane >> 2;
    const int qid  = lane & 3;
    const int tok0 = blockIdx.x * TM;

    float acc[8][4];
    uint32_t cacc[8][2];
#pragma unroll
    for (int nt = 0; nt < 8; nt++) {
#pragma unroll
        for (int i = 0; i < 4; i++) acc[nt][i] = 0.0f;
        cacc[nt][0] = 0u; cacc[nt][1] = 0u;
    }

    // prefetch chunk 0
    float4 px[4];
    uint4  pwh[2], pwl[2];
#pragma unroll
    for (int i = 0; i < 4; i++) {
        int s = tid + i * THREADS; int row = s >> 3; int kq = (s & 7) * 4;
        px[i] = *reinterpret_cast<const float4*>(&x[(size_t)(tok0 + row) * HDIM + kq]);
    }
#pragma unroll
    for (int i = 0; i < 2; i++) {
        int qq = tid + i * THREADS;            // 256 quads
        int row = qq >> 2; int c4 = (qq & 3) * 4;
        pwh[i] = *reinterpret_cast<const uint4*>(&g_whi[row * (HDIM / 2) + c4]);
        pwl[i] = *reinterpret_cast<const uint4*>(&g_wlo[row * (HDIM / 2) + c4]);
    }

    for (int c = 0; c < NCH; c++) {
        const int p = c & 1;
        uint32_t* AH = sm.tiles[p][0];
        uint32_t* AL = sm.tiles[p][1];
        uint32_t* BH = sm.tiles[p][2];
        uint32_t* BL = sm.tiles[p][3];

        // x: convert hi/lo, STS.64
#pragma unroll
        for (int i = 0; i < 4; i++) {
            int s = tid + i * THREADS; int row = s >> 3; int h2b = (s & 7) * 2;
            float4 v = px[i];
            __half2 h0 = __floats2half2_rn(v.x, v.y);
            __half2 h1 = __floats2half2_rn(v.z, v.w);
            float2 f0 = __half22float2(h0);
            float2 f1 = __half22float2(h1);
            __half2 l0 = __floats2half2_rn(v.x - f0.x, v.y - f0.y);
            __half2 l1 = __floats2half2_rn(v.z - f1.x, v.w - f1.y);
            uint32_t hh[2] = {*reinterpret_cast<uint32_t*>(&h0), *reinterpret_cast<uint32_t*>(&h1)};
            uint32_t ll[2] = {*reinterpret_cast<uint32_t*>(&l0), *reinterpret_cast<uint32_t*>(&l1)};
            *reinterpret_cast<uint2*>(&AH[row * RP + h2b]) = *reinterpret_cast<uint2*>(hh);
            *reinterpret_cast<uint2*>(&AL[row * RP + h2b]) = *reinterpret_cast<uint2*>(ll);
        }
        // W: straight copy (already split), STS.128
#pragma unroll
        for (int i = 0; i < 2; i++) {
            int qq = tid + i * THREADS;
            int row = qq >> 2; int c4 = (qq & 3) * 4;
            *reinterpret_cast<uint4*>(&BH[row * RP + c4]) = pwh[i];
            *reinterpret_cast<uint4*>(&BL[row * RP + c4]) = pwl[i];
        }

        // prefetch next chunk
        if (c + 1 < NCH) {
            const int k0f = (c + 1) * KB;           // in halfs == floats index
#pragma unroll
            for (int i = 0; i < 4; i++) {
                int s = tid + i * THREADS; int row = s >> 3; int kq = (s & 7) * 4;
                px[i] = *reinterpret_cast<const float4*>(&x[(size_t)(tok0 + row) * HDIM + k0f + kq]);
            }
            const int k0h = (c + 1) * (KB / 2);     // in half2 units
#pragma unroll
            for (int i = 0; i < 2; i++) {
                int qq = tid + i * THREADS;
                int row = qq >> 2; int c4 = (qq & 3) * 4;
                pwh[i] = *reinterpret_cast<const uint4*>(&g_whi[row * (HDIM / 2) + k0h + c4]);
                pwl[i] = *reinterpret_cast<const uint4*>(&g_wlo[row * (HDIM / 2) + k0h + c4]);
            }
        }
        __syncthreads();

        const int r0 = wid * 16 + grp;
        const int r1 = r0 + 8;
#pragma unroll
        for (int ks = 0; ks < 2; ks++) {
            const int h2k = ks * 8 + qid;
            uint32_t aH[4], aL[4];
            aH[0] = AH[r0 * RP + h2k];     aH[1] = AH[r1 * RP + h2k];
            aH[2] = AH[r0 * RP + h2k + 4]; aH[3] = AH[r1 * RP + h2k + 4];
            aL[0] = AL[r0 * RP + h2k];     aL[1] = AL[r1 * RP + h2k];
            aL[2] = AL[r0 * RP + h2k + 4]; aL[3] = AL[r1 * RP + h2k + 4];
#pragma unroll
            for (int nt = 0; nt < 8; nt++) {
                const int n0 = nt * 8 + grp;
                uint32_t bH0 = BH[n0 * RP + h2k];
                uint32_t bH1 = BH[n0 * RP + h2k + 4];
                uint32_t bL0 = BL[n0 * RP + h2k];
                uint32_t bL1 = BL[n0 * RP + h2k + 4];
                mma_f32acc(acc[nt], aH, bH0, bH1);          // main term, fp32 acc
                mma_f16acc(cacc[nt], aH, bL0, bL1);         // cross terms, fp16 acc
                mma_f16acc(cacc[nt], aL, bH0, bH1);
            }
        }
        __syncthreads();
    }

    // ---- combine cross terms + stash logits ----
    {
        const int r0 = wid * 16 + grp;
        const int r1 = r0 + 8;
#pragma unroll
        for (int nt = 0; nt < 8; nt++) {
            float2 c0 = __half22float2(*reinterpret_cast<__half2*>(&cacc[nt][0]));
            float2 c1 = __half22float2(*reinterpret_cast<__half2*>(&cacc[nt][1]));
            const int cb = nt * 8 + qid * 2;
            sm.ls[r0][cb]     = acc[nt][0] + c0.x;
            sm.ls[r0][cb + 1] = acc[nt][1] + c0.y;
            sm.ls[r1][cb]     = acc[nt][2] + c1.x;
            sm.ls[r1][cb + 1] = acc[nt][3] + c1.y;
        }
    }
    __syncthreads();

    // ---- per-token epilogue ----
    if (tid < TM) {
        float lg[NE];
#pragma unroll
        for (int e = 0; e < NE; e++) lg[e] = sm.ls[tid][e];

        float v1 = -1e30f, v2 = -1e30f, v3 = -1e30f;
        int i1 = 0, i2 = 0;
#pragma unroll
        for (int e = 0; e < NE; e++) {
            float le = lg[e];
            if (le > v1)      { v3 = v2; v2 = v1; i2 = i1; v1 = le; i1 = e; }
            else if (le > v2) { v3 = v2; v2 = le; i2 = e; }
            else if (le > v3) { v3 = le; }
        }
        const int tg = tok0 + tid;

        if ((v1 - v2 < GAP_TH) || (v2 - v3 < GAP_TH)) {
            int slot = atomicAdd(&g_nflag, 1);
            if (slot < FLAG_CAP) {
                g_flags[slot] = tg;
#pragma unroll
                for (int e = 0; e < NE; e++) g_flag_lg[slot][e] = lg[e];
            }
        }

        const float m = v1;
        float s = 0.0f;
#pragma unroll
        for (int e = 0; e < NE; e++) { lg[e] = expf(lg[e] - m); s += lg[e]; }
        const float inv = 1.0f / s;
#pragma unroll
        for (int e = 0; e < NE; e++) sm.ls[tid][e] = lg[e] * inv;

        const float p1 = inv;
        const float p2 = expf(v2 - m) * inv;
        const float s1 = 1.0f / (1.0f + expf(p2 - p1));

        out[tg * 2 + 0] = s1;
        out[tg * 2 + 1] = 1.0f - s1;
        out[2 * N + tg * 2 + 0] = (float)i1;
        out[2 * N + tg * 2 + 1] = (float)i2;

        float lse = m + logf(s);
        float zz = lse * lse;
#pragma unroll
        for (int o = 16; o > 0; o >>= 1)
            zz += __shfl_xor_sync(0xFFFFFFFFu, zz, o);
        if (lane == 0) atomicAdd(&g_zsum, zz);
    }
    __syncthreads();

    if (tid < NE) {
        float cs = 0.0f;
#pragma unroll 8
        for (int t = 0; t < TM; t++) cs += sm.ls[t][tid];
        atomicAdd(&g_eload[tid], cs);
    }
}

// ---------------- candidate-only fp64 fixup ----------------
__global__ __launch_bounds__(128) void fixup_kernel(
    const float* __restrict__ x, const float* __restrict__ W,
    float* __restrict__ out, int N)
{
    __shared__ float  xs[HDIM];
    __shared__ int    cand[16];
    __shared__ int    ncand_sh;
    __shared__ double cval[16];
    __shared__ double wpart[4];
    const int tid = threadIdx.x;
    const int nf  = min(g_nflag, FLAG_CAP);

    for (int fi = blockIdx.x; fi < nf; fi += gridDim.x) {
        const int tg = g_flags[fi];
        const float* lgp = g_flag_lg[fi];

        for (int k = tid; k < HDIM; k += 128)
            xs[k] = x[(size_t)tg * HDIM + k];

        if (tid == 0) {
            float v1 = -1e30f, v2 = -1e30f;
            for (int e = 0; e < NE; e++) {
                float le = lgp[e];
                if (le > v1)      { v2 = v1; v1 = le; }
                else if (le > v2) { v2 = le; }
            }
            float cut = v2 - 2.0f * GAP_TH;
            int nc = 0;
            for (int e = 0; e < NE; e++)
                if (lgp[e] > cut && nc < 16) cand[nc++] = e;
            ncand_sh = nc;
        }
        __syncthreads();
        const int nc = ncand_sh;

        for (int ci = 0; ci < nc; ci++) {
            const float* wr = &W[(size_t)cand[ci] * HDIM];
            double p = 0.0;
            for (int k = tid * 16; k < tid * 16 + 16; k++)
                p += (double)xs[k] * (double)wr[k];
#pragma unroll
            for (int o = 16; o > 0; o >>= 1)
                p += __shfl_xor_sync(0xFFFFFFFFu, p, o);
            if ((tid & 31) == 0) wpart[tid >> 5] = p;
            __syncthreads();
            if (tid == 0) cval[ci] = wpart[0] + wpart[1] + wpart[2] + wpart[3];
            __syncthreads();
        }

        if (tid == 0) {
            double b1 = -1e300, b2 = -1e300; int i1 = 0, i2 = 0;
            for (int ci = 0; ci < nc; ci++) {
                double v = cval[ci]; int e = cand[ci];
                if (v > b1)      { b2 = b1; i2 = i1; b1 = v; i1 = e; }
                else if (v > b2) { b2 = v; i2 = e; }
            }
            float m = lgp[0];
            for (int e = 1; e < NE; e++) m = fmaxf(m, lgp[e]);
            float s = 0.0f;
            for (int e = 0; e < NE; e++) s += expf(lgp[e] - m);
            float inv = 1.0f / s;
            float p1 = expf(lgp[i1] - m) * inv;
            float p2 = expf(lgp[i2] - m) * inv;
            float s1 = 1.0f / (1.0f + expf(p2 - p1));
            out[tg * 2 + 0] = s1;
            out[tg * 2 + 1] = 1.0f - s1;
            out[2 * N + tg * 2 + 0] = (float)i1;
            out[2 * N + tg * 2 + 1] = (float)i2;
        }
        __syncthreads();
    }
}

__global__ void loss_kernel(float* __restrict__ out, int N) {
    __shared__ float sh[NE];
    const int t = threadIdx.x;
    const float invN = 1.0f / (float)N;
    if (t < NE) {
        float d = g_eload[t] * invN - (1.0f / 64.0f);
        sh[t] = d * d;
    }
    __syncthreads();
    if (t == 0) {
        float lb = 0.0f;
#pragma unroll
        for (int e = 0; e < NE; e++) lb += sh[e];
        out[(size_t)4 * N] = 0.01f * lb + 1e-4f * (g_zsum * invN);
    }
}

extern "C" void kernel_launch(void* const* d_in, const int* in_sizes, int n_in,
                              void* d_out, int out_size) {
    const float* x = (const float*)d_in[0];
    const float* W = (const float*)d_in[1];
    float* out = (float*)d_out;
    const int N = in_sizes[0] / HDIM;   // 16384

    zero_kernel<<<1, 64>>>();
    prep_kernel<<<NE, 256>>>(W);
    gate_kernel<<<N / TM, THREADS>>>(x, W, out, N);
    fixup_kernel<<<128, 128>>>(x, W, out, N);
    loss_kernel<<<1, 64>>>(out, N);
}